// round 16
// baseline (speedup 1.0000x reference)
#include <cuda_runtime.h>
#include <cuda_fp16.h>
#include <math.h>
#include <stdint.h>

#define Bx  16
#define Sx  512
#define Vx  512
#define Hx  1024
#define NLx 8
#define NHx 16
#define DHx 64
#define Fx  4096
#define Mx  (Bx*Sx)

#define LOG2E 1.4426950408889634f

// ---------------- scratch ----------------
__device__ float g_x[Mx*Hx];
__device__ half  g_qkv_h[Mx*3*Hx];
__device__ half  g_hh[Mx*Hx];
__device__ half  g_attn_h[Mx*Hx];
__device__ half  g_mid_h[(size_t)Mx*Fx];
__device__ half  g_hhi[Mx*Hx];
__device__ half  g_hlo[Mx*Hx];
__device__ half  g_ehi[Vx*Hx];
__device__ half  g_elo[Vx*Hx];
__device__ half  g_Wqkv_t[(size_t)NLx*3*Hx*Hx];
__device__ half  g_Wo_t[(size_t)NLx*Hx*Hx];
__device__ half  g_Wfc_t[(size_t)NLx*Fx*Hx];
__device__ half  g_Wproj_t[(size_t)NLx*Hx*Fx];

// ---------------- helpers ----------------
__device__ __forceinline__ float ex2(float x) {
    float r;
    asm("ex2.approx.f32 %0, %1;" : "=f"(r) : "f"(x));
    return r;
}
__device__ __forceinline__ void mma_f16(float* c, const uint32_t* a, const uint32_t* b) {
    asm volatile(
        "mma.sync.aligned.m16n8k16.row.col.f32.f16.f16.f32 "
        "{%0,%1,%2,%3}, {%4,%5,%6,%7}, {%8,%9}, {%0,%1,%2,%3};\n"
        : "+f"(c[0]), "+f"(c[1]), "+f"(c[2]), "+f"(c[3])
        : "r"(a[0]), "r"(a[1]), "r"(a[2]), "r"(a[3]), "r"(b[0]), "r"(b[1]));
}
__device__ __forceinline__ void ldsm_x4(uint32_t& r0, uint32_t& r1, uint32_t& r2, uint32_t& r3,
                                        uint32_t addr) {
    asm volatile("ldmatrix.sync.aligned.m8n8.x4.shared.b16 {%0,%1,%2,%3}, [%4];"
                 : "=r"(r0), "=r"(r1), "=r"(r2), "=r"(r3) : "r"(addr));
}
__device__ __forceinline__ void ldsm_x4_t(uint32_t& r0, uint32_t& r1, uint32_t& r2, uint32_t& r3,
                                          uint32_t addr) {
    asm volatile("ldmatrix.sync.aligned.m8n8.x4.trans.shared.b16 {%0,%1,%2,%3}, [%4];"
                 : "=r"(r0), "=r"(r1), "=r"(r2), "=r"(r3) : "r"(addr));
}
__device__ __forceinline__ void cp_async16(void* smem_dst, const void* gmem_src) {
    uint32_t s = (uint32_t)__cvta_generic_to_shared(smem_dst);
    asm volatile("cp.async.cg.shared.global [%0], [%1], 16;\n" :: "r"(s), "l"(gmem_src));
}
__device__ __forceinline__ void cp_commit() { asm volatile("cp.async.commit_group;\n"); }
__device__ __forceinline__ void cp_wait0() { asm volatile("cp.async.wait_group 0;\n"); }
__device__ __forceinline__ void cp_wait2() { asm volatile("cp.async.wait_group 2;\n"); }
__device__ __forceinline__ float gelu_f(float v) {
    return 0.5f * v * (1.0f + tanhf(0.7978845608028654f * (v + 0.044715f * v * v * v)));
}

// ------- weight transpose+convert: 128n x 64k tiles, f4 loads, 16B stores ---
__global__ __launch_bounds__(256) void wtrans_kernel(const float* __restrict__ W,
                                                     half* __restrict__ Wt,
                                                     int K, int N) {
    __shared__ float tile[64][132];
    const size_t lsz = (size_t)K * N;
    const float* Wl = W + blockIdx.z * lsz;
    half* Wtl = Wt + blockIdx.z * lsz;
    const int n0 = blockIdx.x * 128, k0 = blockIdx.y * 64;
    const int t = threadIdx.x;
    {
        int c4 = (t & 31) * 4, r = t >> 5;   // 8 rows per pass, 8 passes
#pragma unroll
        for (int i = 0; i < 8; i++) {
            float4 v = *(const float4*)(Wl + (size_t)(k0 + r + i * 8) * N + n0 + c4);
            *(float4*)&tile[r + i * 8][c4] = v;
        }
    }
    __syncthreads();
    {
        int nrow = t >> 1, kc = (t & 1) * 32;   // 128 n-rows, 2 threads/row
        half2 hv[16];
#pragma unroll
        for (int j = 0; j < 16; j++)
            hv[j] = __floats2half2_rn(tile[kc + 2 * j][nrow], tile[kc + 2 * j + 1][nrow]);
#pragma unroll
        for (int u = 0; u < 4; u++)
            *(uint4*)&Wtl[(size_t)(n0 + nrow) * K + k0 + kc + u * 8] = *(uint4*)&hv[u * 4];
    }
}

// ---------------- emb hi/lo split ----------------
__global__ __launch_bounds__(256) void esplit_kernel(const float* __restrict__ src,
                                                     half* __restrict__ hi,
                                                     half* __restrict__ lo) {
    int idx = blockIdx.x * 256 + threadIdx.x;
    float4 v = ((const float4*)src)[idx];
    half h0 = __float2half_rn(v.x), h1 = __float2half_rn(v.y);
    half h2 = __float2half_rn(v.z), h3 = __float2half_rn(v.w);
    half2 hh0; hh0.x = h0; hh0.y = h1;
    half2 hh1; hh1.x = h2; hh1.y = h3;
    *(half2*)(hi + idx * 4) = hh0; *(half2*)(hi + idx * 4 + 2) = hh1;
    *(half2*)(lo + idx * 4) =
        __floats2half2_rn(v.x - __half2float(h0), v.y - __half2float(h1));
    *(half2*)(lo + idx * 4 + 2) =
        __floats2half2_rn(v.z - __half2float(h2), v.w - __half2float(h3));
}

// ---------------- embedding ----------------
__global__ __launch_bounds__(256) void embed_kernel(const int* __restrict__ ids,
                                                    const float* __restrict__ emb,
                                                    float* __restrict__ out) {
    int m = blockIdx.x, t = threadIdx.x;
    int id = ids[m];
    ((float4*)(out + (size_t)m * Hx))[t] = ((const float4*)(emb + (size_t)id * Hx))[t];
}

// ---------------- layernorm: warp-per-row; MODE 1=half, 2=hi/lo halves ------
template<int MODE>
__global__ __launch_bounds__(256) void ln_kernel(const float* __restrict__ x,
                                                 const float* __restrict__ g,
                                                 const float* __restrict__ b,
                                                 half* __restrict__ outh,
                                                 half* __restrict__ outl) {
    const int lane = threadIdx.x & 31;
    const int m = blockIdx.x * 8 + (threadIdx.x >> 5);
    const float4* xr = (const float4*)(x + (size_t)m * Hx);

    float4 v[8];
    float s = 0.f;
#pragma unroll
    for (int i = 0; i < 8; i++) {
        v[i] = xr[lane + i * 32];
        s += v[i].x + v[i].y + v[i].z + v[i].w;
    }
#pragma unroll
    for (int o = 16; o; o >>= 1) s += __shfl_xor_sync(0xffffffffu, s, o);
    float mu = s * (1.0f / Hx);

    float s2 = 0.f;
#pragma unroll
    for (int i = 0; i < 8; i++) {
        float d0 = v[i].x - mu, d1 = v[i].y - mu, d2 = v[i].z - mu, d3 = v[i].w - mu;
        s2 += d0*d0 + d1*d1 + d2*d2 + d3*d3;
    }
#pragma unroll
    for (int o = 16; o; o >>= 1) s2 += __shfl_xor_sync(0xffffffffu, s2, o);
    float inv = rsqrtf(s2 * (1.0f / Hx) + 1e-5f);

#pragma unroll
    for (int i = 0; i < 8; i++) {
        float4 gg = ((const float4*)g)[lane + i * 32];
        float4 bb = ((const float4*)b)[lane + i * 32];
        float o0 = (v[i].x - mu) * inv * gg.x + bb.x;
        float o1 = (v[i].y - mu) * inv * gg.y + bb.y;
        float o2 = (v[i].z - mu) * inv * gg.z + bb.z;
        float o3 = (v[i].w - mu) * inv * gg.w + bb.w;
        int c = (lane + i * 32) * 4;
        if (MODE == 1) {
            *(half2*)(outh + (size_t)m * Hx + c) = __floats2half2_rn(o0, o1);
            *(half2*)(outh + (size_t)m * Hx + c + 2) = __floats2half2_rn(o2, o3);
        } else {
            half h0 = __float2half_rn(o0), h1 = __float2half_rn(o1);
            half h2 = __float2half_rn(o2), h3 = __float2half_rn(o3);
            half2 hh0; hh0.x = h0; hh0.y = h1;
            half2 hh1; hh1.x = h2; hh1.y = h3;
            *(half2*)(outh + (size_t)m * Hx + c) = hh0;
            *(half2*)(outh + (size_t)m * Hx + c + 2) = hh1;
            *(half2*)(outl + (size_t)m * Hx + c) =
                __floats2half2_rn(o0 - __half2float(h0), o1 - __half2float(h1));
            *(half2*)(outl + (size_t)m * Hx + c + 2) =
                __floats2half2_rn(o2 - __half2float(h2), o3 - __half2float(h3));
        }
    }
}

// ======= fp16 GEMM, 4-stage cp.async + ldmatrix =============================
#define HST 40
#define NSTAGE 4
#define STG_HALVES (128 * HST)
#define GEMM_SMEM (NSTAGE * 2 * STG_HALVES * 2)

template<bool GELU, bool RESID, bool OUT_HALF>
__global__ __launch_bounds__(256, 2) void gemm_h16(const half* __restrict__ A,
                                                   const half* __restrict__ Bw,
                                                   const float* __restrict__ bias,
                                                   const float* __restrict__ R,
                                                   float* __restrict__ C,
                                                   half* __restrict__ Ch,
                                                   int M, int N, int K) {
    extern __shared__ half smh[];
    const int t = threadIdx.x;
    const int warp = t >> 5, lane = t & 31;
    const int g = lane >> 2, q = lane & 3;
    const int wm = warp >> 1, wn = warp & 1;
    const int m0 = blockIdx.y * 128, n0 = blockIdx.x * 128;

    const int f_row = t >> 1, f_ch = (t & 1) * 16;
    const uint32_t smbase = (uint32_t)__cvta_generic_to_shared(smh);

    const int a_off = (wm * 32 + (lane & 15)) * HST + (lane >> 4) * 8;
    const int b_off = (wn * 64 + ((lane >> 4) * 8) + (lane & 7)) * HST + ((lane >> 3) & 1) * 8;

    float acc[2][8][4];
#pragma unroll
    for (int mt = 0; mt < 2; mt++)
#pragma unroll
        for (int nt = 0; nt < 8; nt++)
#pragma unroll
            for (int r = 0; r < 4; r++) acc[mt][nt][r] = 0.f;

    const half* Arow = A + (size_t)(m0 + f_row) * K + f_ch;
    const half* Brow = Bw + (size_t)(n0 + f_row) * K + f_ch;

#pragma unroll
    for (int s = 0; s < NSTAGE - 1; s++) {
        half* as = smh + s * 2 * STG_HALVES;
        half* bs = as + STG_HALVES;
        cp_async16(&as[f_row * HST + f_ch],     Arow + s * 32);
        cp_async16(&as[f_row * HST + f_ch + 8], Arow + s * 32 + 8);
        cp_async16(&bs[f_row * HST + f_ch],     Brow + s * 32);
        cp_async16(&bs[f_row * HST + f_ch + 8], Brow + s * 32 + 8);
        cp_commit();
    }

    const int T = K >> 5;
    for (int i = 0; i < T; i++) {
        const int s = i & (NSTAGE - 1);
        cp_wait2();
        __syncthreads();

        if (i + NSTAGE - 1 < T) {
            const int sn = (i + NSTAGE - 1) & (NSTAGE - 1);
            const int kn = (i + NSTAGE - 1) * 32;
            half* as = smh + sn * 2 * STG_HALVES;
            half* bs = as + STG_HALVES;
            cp_async16(&as[f_row * HST + f_ch],     Arow + kn);
            cp_async16(&as[f_row * HST + f_ch + 8], Arow + kn + 8);
            cp_async16(&bs[f_row * HST + f_ch],     Brow + kn);
            cp_async16(&bs[f_row * HST + f_ch + 8], Brow + kn + 8);
        }
        cp_commit();

        const uint32_t as_b = smbase + (uint32_t)(s * 2 * STG_HALVES) * 2;
        const uint32_t bs_b = as_b + (uint32_t)STG_HALVES * 2;
#pragma unroll
        for (int ks = 0; ks < 2; ks++) {
            const int k = ks * 16;
            uint32_t af[2][4], bf[8][2];
#pragma unroll
            for (int mt = 0; mt < 2; mt++)
                ldsm_x4(af[mt][0], af[mt][1], af[mt][2], af[mt][3],
                        as_b + (uint32_t)(a_off + mt * 16 * HST + k) * 2);
#pragma unroll
            for (int p = 0; p < 4; p++)
                ldsm_x4(bf[2*p][0], bf[2*p][1], bf[2*p+1][0], bf[2*p+1][1],
                        bs_b + (uint32_t)(b_off + p * 16 * HST + k) * 2);
#pragma unroll
            for (int mt = 0; mt < 2; mt++)
#pragma unroll
                for (int nt = 0; nt < 8; nt++)
                    mma_f16(acc[mt][nt], af[mt], bf[nt]);
        }
    }

#pragma unroll
    for (int mt = 0; mt < 2; mt++) {
#pragma unroll
        for (int nt = 0; nt < 8; nt++) {
            int r0 = m0 + wm * 32 + mt * 16 + g;
            int c0 = n0 + wn * 64 + nt * 8 + q * 2;
            float b0 = bias ? bias[c0] : 0.f;
            float b1 = bias ? bias[c0 + 1] : 0.f;
#pragma unroll
            for (int hf = 0; hf < 2; hf++) {
                int row = r0 + hf * 8;
                float v0 = acc[mt][nt][hf * 2 + 0] + b0;
                float v1 = acc[mt][nt][hf * 2 + 1] + b1;
                if (GELU) { v0 = gelu_f(v0); v1 = gelu_f(v1); }
                if (RESID) {
                    const float2 rr = *(const float2*)(R + (size_t)row * N + c0);
                    v0 += rr.x; v1 += rr.y;
                }
                if (OUT_HALF) {
                    *(half2*)(Ch + (size_t)row * N + c0) = __floats2half2_rn(v0, v1);
                } else {
                    float2 o2; o2.x = v0; o2.y = v1;
                    *(float2*)(C + (size_t)row * N + c0) = o2;
                }
            }
        }
    }
}

// ---- fused flash attention: fp16 HMMA, 64-q tiles + masked-tile skip -------
#define AHS 72
#define ATTN_SMEM_BYTES (4 * 64 * AHS * 2)   // 36864

__global__ __launch_bounds__(128) void attn_kernel(const half* __restrict__ qkv,
                                                   const int* __restrict__ sp,
                                                   half* __restrict__ attn) {
    extern __shared__ half smah[];
    half* Qs = smah;
    half* Ks = Qs + 64 * AHS;
    half* Vs = Ks + 64 * AHS;
    half* Ps = Vs + 64 * AHS;
    const uint32_t qs_b = (uint32_t)__cvta_generic_to_shared(Qs);
    const uint32_t ks_b = (uint32_t)__cvta_generic_to_shared(Ks);
    const uint32_t vs_b = (uint32_t)__cvta_generic_to_shared(Vs);
    const uint32_t ps_b = (uint32_t)__cvta_generic_to_shared(Ps);

    const int it = blockIdx.x, bn = blockIdx.y;
    const int b = bn >> 4, n = bn & 15;
    const int t = threadIdx.x, w = t >> 5, lane = t & 31;
    const int g = lane >> 2, q = lane & 3;
    const int i0 = it * 64;
    const int spv = sp[b];
    const float slope2 = exp2f(-0.5f * (float)(n + 1)) * LOG2E;
    const float qs2 = 0.125f * LOG2E;

#pragma unroll
    for (int l = 0; l < 4; l++) {
        int e = t + l * 128;
        int row = e >> 3, c8 = (e & 7) * 8;
        cp_async16(&Qs[row * AHS + c8],
                   qkv + (size_t)(b * Sx + i0 + row) * 3072 + n * 64 + c8);
    }
    cp_commit();
    cp_wait0();
    __syncthreads();

    const int r0 = w * 16 + g;
    const int a_off = (w * 16 + (lane & 15)) * AHS + (lane >> 4) * 8;
    uint32_t qf[4][4];
#pragma unroll
    for (int kk = 0; kk < 4; kk++)
        ldsm_x4(qf[kk][0], qf[kk][1], qf[kk][2], qf[kk][3],
                qs_b + (uint32_t)(a_off + kk * 16) * 2);

    const int bk_off = (((lane >> 4) * 8) + (lane & 7)) * AHS + ((lane >> 3) & 1) * 8;
    const int vt_off = (((lane >> 3) & 1) * 8 + (lane & 7)) * AHS + (lane >> 4) * 8;

    float o[8][4];
#pragma unroll
    for (int nt = 0; nt < 8; nt++)
#pragma unroll
        for (int c = 0; c < 4; c++) o[nt][c] = 0.f;
    float m0 = -1e30f, m1 = -1e30f, l0 = 0.f, l1 = 0.f;

    const int rowA = i0 + r0, rowB = rowA + 8;

    for (int jt = 0; jt <= it; jt++) {
        const int j0 = jt * 64;
        // fully-masked tile skip (CTA-uniform; contributes exactly zero)
        if (i0 >= spv && j0 + 64 <= spv) continue;

        __syncthreads();   // previous PV done -> Ks/Vs reusable
#pragma unroll
        for (int l = 0; l < 4; l++) {
            int e = t + l * 128;
            int row = e >> 3, c8 = (e & 7) * 8;
            const half* base = qkv + (size_t)(b * Sx + j0 + row) * 3072 + n * 64 + c8;
            cp_async16(&Ks[row * AHS + c8], base + 1024);
            cp_async16(&Vs[row * AHS + c8], base + 2048);
        }
        cp_commit();
        cp_wait0();
        __syncthreads();

        // ---- QK^T
        float s[8][4];
#pragma unroll
        for (int nt = 0; nt < 8; nt++)
#pragma unroll
            for (int c = 0; c < 4; c++) s[nt][c] = 0.f;
#pragma unroll
        for (int kk = 0; kk < 4; kk++) {
            uint32_t bf[8][2];
#pragma unroll
            for (int p = 0; p < 4; p++)
                ldsm_x4(bf[2*p][0], bf[2*p][1], bf[2*p+1][0], bf[2*p+1][1],
                        ks_b + (uint32_t)(bk_off + p * 16 * AHS + kk * 16) * 2);
#pragma unroll
            for (int nt = 0; nt < 8; nt++)
                mma_f16(s[nt], qf[kk], bf[nt]);
        }

        // ---- scale + bias + mask (log2 domain)
#pragma unroll
        for (int nt = 0; nt < 8; nt++) {
#pragma unroll
            for (int c = 0; c < 4; c++) {
                int i = (c < 2) ? rowA : rowB;
                int j = j0 + nt * 8 + 2 * q + (c & 1);
                bool allowed = (j <= i) && !((i >= spv) && (j < spv));
                s[nt][c] = allowed ? fmaf(s[nt][c], qs2, -slope2 * (float)(i - j)) : -1e30f;
            }
        }

        // ---- online softmax
        float mx0 = -1e30f, mx1 = -1e30f;
#pragma unroll
        for (int nt = 0; nt < 8; nt++) {
            mx0 = fmaxf(mx0, fmaxf(s[nt][0], s[nt][1]));
            mx1 = fmaxf(mx1, fmaxf(s[nt][2], s[nt][3]));
        }
        mx0 = fmaxf(mx0, __shfl_xor_sync(0xffffffffu, mx0, 1));
        mx0 = fmaxf(mx0, __shfl_xor_sync(0xffffffffu, mx0, 2));
        mx1 = fmaxf(mx1, __shfl_xor_sync(0xffffffffu, mx1, 1));
        mx1 = fmaxf(mx1, __shfl_xor_sync(0xffffffffu, mx1, 2));
        float mn0 = fmaxf(m0, mx0), mn1 = fmaxf(m1, mx1);
        float al0 = ex2(m0 - mn0), al1 = ex2(m1 - mn1);

        float sum0 = 0.f, sum1 = 0.f;
#pragma unroll
        for (int nt = 0; nt < 8; nt++) {
            float p0 = ex2(s[nt][0] - mn0);
            float p1 = ex2(s[nt][1] - mn0);
            float p2 = ex2(s[nt][2] - mn1);
            float p3 = ex2(s[nt][3] - mn1);
            sum0 += p0 + p1; sum1 += p2 + p3;
            *(half2*)&Ps[(r0    ) * AHS + nt * 8 + 2 * q] = __floats2half2_rn(p0, p1);
            *(half2*)&Ps[(r0 + 8) * AHS + nt * 8 + 2 * q] = __floats2half2_rn(p2, p3);
        }
        sum0 += __shfl_xor_sync(0xffffffffu, sum0, 1);
        sum0 += __shfl_xor_sync(0xffffffffu, sum0, 2);
        sum1 += __shfl_xor_sync(0xffffffffu, sum1, 1);
        sum1 += __shfl_xor_sync(0xffffffffu, sum1, 2);
        l0 = l0 * al0 + sum0;
        l1 = l1 * al1 + sum1;
        m0 = mn0; m1 = mn1;
#pragma unroll
        for (int nt = 0; nt < 8; nt++) {
            o[nt][0] *= al0; o[nt][1] *= al0;
            o[nt][2] *= al1; o[nt][3] *= al1;
        }
        __syncwarp();

        // ---- P @ V
#pragma unroll
        for (int kk = 0; kk < 4; kk++) {
            uint32_t pf[4];
            ldsm_x4(pf[0], pf[1], pf[2], pf[3],
                    ps_b + (uint32_t)(a_off + kk * 16) * 2);
            uint32_t bf[8][2];
#pragma unroll
            for (int p = 0; p < 4; p++)
                ldsm_x4_t(bf[2*p][0], bf[2*p][1], bf[2*p+1][0], bf[2*p+1][1],
                          vs_b + (uint32_t)(vt_off + kk * 16 * AHS + p * 16) * 2);
#pragma unroll
            for (int nt = 0; nt < 8; nt++)
                mma_f16(o[nt], pf, bf[nt]);
        }
    }

    const float inv0 = 1.0f / l0, inv1 = 1.0f / l1;
#pragma unroll
    for (int nt = 0; nt < 8; nt++) {
        *(half2*)(attn + (size_t)(b * Sx + rowA) * Hx + n * 64 + nt * 8 + 2 * q) =
            __floats2half2_rn(o[nt][0] * inv0, o[nt][1] * inv0);
        *(half2*)(attn + (size_t)(b * Sx + rowB) * Hx + n * 64 + nt * 8 + 2 * q) =
            __floats2half2_rn(o[nt][2] * inv1, o[nt][3] * inv1);
    }
}

// ---------------- logits: fp16 hi/lo 3-term GEMM, 2-stage ------------------
#define L3_STG (128 * HST)
#define L3_STAGE (4 * L3_STG)
#define L3_SMEM (2 * L3_STAGE * 2)

__global__ __launch_bounds__(256) void gemm_logits3(const half* __restrict__ Ahi,
                                                    const half* __restrict__ Alo,
                                                    const half* __restrict__ Bhi,
                                                    const half* __restrict__ Blo,
                                                    float* __restrict__ C,
                                                    int M, int N, int K) {
    extern __shared__ half smh[];
    const int t = threadIdx.x;
    const int warp = t >> 5, lane = t & 31;
    const int g = lane >> 2, q = lane & 3;
    const int wm = warp >> 1, wn = warp & 1;
    const int m0 = blockIdx.y * 128, n0 = blockIdx.x * 128;

    const int f_row = t >> 1, f_ch = (t & 1) * 16;
    const uint32_t smbase = (uint32_t)__cvta_generic_to_shared(smh);

    const int a_off = (wm * 32 + (lane & 15)) * HST + (lane >> 4) * 8;
    const int b_off = (wn * 64 + ((lane >> 4) * 8) + (lane & 7)) * HST + ((lane >> 3) & 1) * 8;

    float acc[2][8][4];
#pragma unroll
    for (int mt = 0; mt < 2; mt++)
#pragma unroll
        for (int nt = 0; nt < 8; nt++)
#pragma unroll
            for (int r = 0; r < 4; r++) acc[mt][nt][r] = 0.f;

    const half* ArH = Ahi + (size_t)(m0 + f_row) * K + f_ch;
    const half* ArL = Alo + (size_t)(m0 + f_row) * K + f_ch;
    const half* BrH = Bhi + (size_t)(n0 + f_row) * K + f_ch;
    const half* BrL = Blo + (size_t)(n0 + f_row) * K + f_ch;
    const int so = f_row * HST + f_ch;

    {
        half* st = smh;
        cp_async16(&st[so], ArH);                     cp_async16(&st[so + 8], ArH + 8);
        cp_async16(&st[L3_STG + so], ArL);            cp_async16(&st[L3_STG + so + 8], ArL + 8);
        cp_async16(&st[2 * L3_STG + so], BrH);        cp_async16(&st[2 * L3_STG + so + 8], BrH + 8);
        cp_async16(&st[3 * L3_STG + so], BrL);        cp_async16(&st[3 * L3_STG + so + 8], BrL + 8);
        cp_commit();
    }

    const int T = K >> 5;
    for (int i = 0; i < T; i++) {
        cp_wait0();
        __syncthreads();

        if (i + 1 < T) {
            const int kn = (i + 1) * 32;
            half* st = smh + ((i + 1) & 1) * L3_STAGE;
            cp_async16(&st[so], ArH + kn);                cp_async16(&st[so + 8], ArH + kn + 8);
            cp_async16(&st[L3_STG + so], ArL + kn);       cp_async16(&st[L3_STG + so + 8], ArL + kn + 8);
            cp_async16(&st[2 * L3_STG + so], BrH + kn);   cp_async16(&st[2 * L3_STG + so + 8], BrH + kn + 8);
            cp_async16(&st[3 * L3_STG + so], BrL + kn);   cp_async16(&st[3 * L3_STG + so + 8], BrL + kn + 8);
        }
        cp_commit();

        const uint32_t st_b  = smbase + (uint32_t)((i & 1) * L3_STAGE) * 2;
        const uint32_t ah_b = st_b;
        const uint32_t al_b = st_b + (uint32_t)L3_STG * 2;
        const uint32_t bh_b = st_b + (uint32_t)(2 * L3_STG) * 2;
        const uint32_t bl_b = st_b + (uint32_t)(3 * L3_STG) * 2;
#pragma unroll
        for (int ks = 0; ks < 2; ks++) {
            const int k = ks * 16;
            uint32_t ah[2][4], al[2][4], bh[8][2], bl[8][2];
#pragma unroll
            for (int mt = 0; mt < 2; mt++) {
                ldsm_x4(ah[mt][0], ah[mt][1], ah[mt][2], ah[mt][3],
                        ah_b + (uint32_t)(a_off + mt * 16 * HST + k) * 2);
                ldsm_x4(al[mt][0], al[mt][1], al[mt][2], al[mt][3],
                        al_b + (uint32_t)(a_off + mt * 16 * HST + k) * 2);
            }
#pragma unroll
            for (int p = 0; p < 4; p++) {
                ldsm_x4(bh[2*p][0], bh[2*p][1], bh[2*p+1][0], bh[2*p+1][1],
                        bh_b + (uint32_t)(b_off + p * 16 * HST + k) * 2);
                ldsm_x4(bl[2*p][0], bl[2*p][1], bl[2*p+1][0], bl[2*p+1][1],
                        bl_b + (uint32_t)(b_off + p * 16 * HST + k) * 2);
            }
#pragma unroll
            for (int mt = 0; mt < 2; mt++)
#pragma unroll
                for (int nt = 0; nt < 8; nt++) {
                    mma_f16(acc[mt][nt], ah[mt], bl[nt]);
                    mma_f16(acc[mt][nt], al[mt], bh[nt]);
                    mma_f16(acc[mt][nt], ah[mt], bh[nt]);
                }
        }
    }

#pragma unroll
    for (int mt = 0; mt < 2; mt++) {
#pragma unroll
        for (int nt = 0; nt < 8; nt++) {
            int r0 = m0 + wm * 32 + mt * 16 + g;
            int c0 = n0 + wn * 64 + nt * 8 + q * 2;
#pragma unroll
            for (int hf = 0; hf < 2; hf++) {
                int row = r0 + hf * 8;
                float2 o2;
                o2.x = acc[mt][nt][hf * 2 + 0];
                o2.y = acc[mt][nt][hf * 2 + 1];
                *(float2*)(C + (size_t)row * N + c0) = o2;
            }
        }
    }
}

// ---------------- launcher ----------------
extern "C" void kernel_launch(void* const* d_in, const int* in_sizes, int n_in,
                              void* d_out, int out_size) {
    const int*   ids    = (const int*)d_in[0];
    const int*   sp     = (const int*)d_in[1];
    const float* emb    = (const float*)d_in[2];
    const float* ln1_g  = (const float*)d_in[3];
    const float* ln1_b  = (const float*)d_in[4];
    const float* Wqkv   = (const float*)d_in[5];
    const float* bqkv   = (const float*)d_in[6];
    const float* Wo     = (const float*)d_in[7];
    const float* bo     = (const float*)d_in[8];
    const float* ln2_g  = (const float*)d_in[9];
    const float* ln2_b  = (const float*)d_in[10];
    const float* Wfc    = (const float*)d_in[11];
    const float* bfc    = (const float*)d_in[12];
    const float* Wproj  = (const float*)d_in[13];
    const float* bproj  = (const float*)d_in[14];
    const float* lnf_g  = (const float*)d_in[15];
    const float* lnf_b  = (const float*)d_in[16];
    float* out = (float*)d_out;

    float* x;
    half *qkv_h, *hh, *attn_h, *mid_h, *hhi, *hlo, *ehi, *elo;
    half *wqkv_t, *wo_t, *wfc_t, *wproj_t;
    cudaGetSymbolAddress((void**)&x,       g_x);
    cudaGetSymbolAddress((void**)&qkv_h,   g_qkv_h);
    cudaGetSymbolAddress((void**)&hh,      g_hh);
    cudaGetSymbolAddress((void**)&attn_h,  g_attn_h);
    cudaGetSymbolAddress((void**)&mid_h,   g_mid_h);
    cudaGetSymbolAddress((void**)&hhi,     g_hhi);
    cudaGetSymbolAddress((void**)&hlo,     g_hlo);
    cudaGetSymbolAddress((void**)&ehi,     g_ehi);
    cudaGetSymbolAddress((void**)&elo,     g_elo);
    cudaGetSymbolAddress((void**)&wqkv_t,  g_Wqkv_t);
    cudaGetSymbolAddress((void**)&wo_t,    g_Wo_t);
    cudaGetSymbolAddress((void**)&wfc_t,   g_Wfc_t);
    cudaGetSymbolAddress((void**)&wproj_t, g_Wproj_t);

    cudaFuncSetAttribute(attn_kernel, cudaFuncAttributeMaxDynamicSharedMemorySize, ATTN_SMEM_BYTES);
    cudaFuncSetAttribute(gemm_h16<false, false, true>,  cudaFuncAttributeMaxDynamicSharedMemorySize, GEMM_SMEM);
    cudaFuncSetAttribute(gemm_h16<false, true, false>,  cudaFuncAttributeMaxDynamicSharedMemorySize, GEMM_SMEM);
    cudaFuncSetAttribute(gemm_h16<true, false, true>,   cudaFuncAttributeMaxDynamicSharedMemorySize, GEMM_SMEM);
    cudaFuncSetAttribute(gemm_logits3, cudaFuncAttributeMaxDynamicSharedMemorySize, L3_SMEM);

    wtrans_kernel<<<dim3(3 * Hx / 128, Hx / 64, NLx), 256>>>(Wqkv, wqkv_t, Hx, 3 * Hx);
    wtrans_kernel<<<dim3(Hx / 128, Hx / 64, NLx), 256>>>(Wo, wo_t, Hx, Hx);
    wtrans_kernel<<<dim3(Fx / 128, Hx / 64, NLx), 256>>>(Wfc, wfc_t, Hx, Fx);
    wtrans_kernel<<<dim3(Hx / 128, Fx / 64, NLx), 256>>>(Wproj, wproj_t, Fx, Hx);
    esplit_kernel<<<(Vx * Hx / 4) / 256, 256>>>(emb, ehi, elo);

    embed_kernel<<<Mx, 256>>>(ids, emb, x);

    for (int l = 0; l < NLx; l++) {
        ln_kernel<1><<<Mx / 8, 256>>>(x, ln1_g + l * Hx, ln1_b + l * Hx, hh, nullptr);
        gemm_h16<false, false, true><<<dim3(3 * Hx / 128, Mx / 128), 256, GEMM_SMEM>>>(
            hh, wqkv_t + (size_t)l * 3 * Hx * Hx, bqkv + (size_t)l * 3 * Hx, nullptr,
            nullptr, qkv_h, Mx, 3 * Hx, Hx);
        attn_kernel<<<dim3(Sx / 64, Bx * NHx), 128, ATTN_SMEM_BYTES>>>(qkv_h, sp, attn_h);
        gemm_h16<false, true, false><<<dim3(Hx / 128, Mx / 128), 256, GEMM_SMEM>>>(
            attn_h, wo_t + (size_t)l * Hx * Hx, bo + (size_t)l * Hx, x,
            x, nullptr, Mx, Hx, Hx);
        ln_kernel<1><<<Mx / 8, 256>>>(x, ln2_g + l * Hx, ln2_b + l * Hx, hh, nullptr);
        gemm_h16<true, false, true><<<dim3(Fx / 128, Mx / 128), 256, GEMM_SMEM>>>(
            hh, wfc_t + (size_t)l * Fx * Hx, bfc + (size_t)l * Fx, nullptr,
            nullptr, mid_h, Mx, Fx, Hx);
        gemm_h16<false, true, false><<<dim3(Hx / 128, Mx / 128), 256, GEMM_SMEM>>>(
            mid_h, wproj_t + (size_t)l * Hx * Fx, bproj + (size_t)l * Hx, x,
            x, nullptr, Mx, Hx, Fx);
    }

    ln_kernel<2><<<Mx / 8, 256>>>(x, lnf_g, lnf_b, hhi, hlo);
    gemm_logits3<<<dim3(Vx / 128, Mx / 128), 256, L3_SMEM>>>(
        hhi, hlo, ehi, elo, out, Mx, Vx, Hx);
}

// round 17
// speedup vs baseline: 1.0100x; 1.0100x over previous
#include <cuda_runtime.h>
#include <cuda_fp16.h>
#include <math.h>
#include <stdint.h>

#define Bx  16
#define Sx  512
#define Vx  512
#define Hx  1024
#define NLx 8
#define NHx 16
#define DHx 64
#define Fx  4096
#define Mx  (Bx*Sx)

#define LOG2E 1.4426950408889634f

// ---------------- scratch ----------------
__device__ float g_x[Mx*Hx];
__device__ half  g_qkv_h[Mx*3*Hx];
__device__ half  g_hh[Mx*Hx];
__device__ half  g_attn_h[Mx*Hx];
__device__ half  g_mid_h[(size_t)Mx*Fx];
__device__ half  g_hhi[Mx*Hx];
__device__ half  g_hlo[Mx*Hx];
__device__ half  g_ehi[Vx*Hx];
__device__ half  g_elo[Vx*Hx];
__device__ half  g_Wqkv_t[(size_t)NLx*3*Hx*Hx];
__device__ half  g_Wo_t[(size_t)NLx*Hx*Hx];
__device__ half  g_Wfc_t[(size_t)NLx*Fx*Hx];
__device__ half  g_Wproj_t[(size_t)NLx*Hx*Fx];

// ---------------- helpers ----------------
__device__ __forceinline__ float ex2(float x) {
    float r;
    asm("ex2.approx.f32 %0, %1;" : "=f"(r) : "f"(x));
    return r;
}
__device__ __forceinline__ void mma_f16(float* c, const uint32_t* a, const uint32_t* b) {
    asm volatile(
        "mma.sync.aligned.m16n8k16.row.col.f32.f16.f16.f32 "
        "{%0,%1,%2,%3}, {%4,%5,%6,%7}, {%8,%9}, {%0,%1,%2,%3};\n"
        : "+f"(c[0]), "+f"(c[1]), "+f"(c[2]), "+f"(c[3])
        : "r"(a[0]), "r"(a[1]), "r"(a[2]), "r"(a[3]), "r"(b[0]), "r"(b[1]));
}
__device__ __forceinline__ void ldsm_x4(uint32_t& r0, uint32_t& r1, uint32_t& r2, uint32_t& r3,
                                        uint32_t addr) {
    asm volatile("ldmatrix.sync.aligned.m8n8.x4.shared.b16 {%0,%1,%2,%3}, [%4];"
                 : "=r"(r0), "=r"(r1), "=r"(r2), "=r"(r3) : "r"(addr));
}
__device__ __forceinline__ void ldsm_x4_t(uint32_t& r0, uint32_t& r1, uint32_t& r2, uint32_t& r3,
                                          uint32_t addr) {
    asm volatile("ldmatrix.sync.aligned.m8n8.x4.trans.shared.b16 {%0,%1,%2,%3}, [%4];"
                 : "=r"(r0), "=r"(r1), "=r"(r2), "=r"(r3) : "r"(addr));
}
__device__ __forceinline__ void cp_async16(void* smem_dst, const void* gmem_src) {
    uint32_t s = (uint32_t)__cvta_generic_to_shared(smem_dst);
    asm volatile("cp.async.cg.shared.global [%0], [%1], 16;\n" :: "r"(s), "l"(gmem_src));
}
__device__ __forceinline__ void cp_commit() { asm volatile("cp.async.commit_group;\n"); }
__device__ __forceinline__ void cp_wait0() { asm volatile("cp.async.wait_group 0;\n"); }
__device__ __forceinline__ void cp_wait2() { asm volatile("cp.async.wait_group 2;\n"); }
__device__ __forceinline__ float gelu_f(float v) {
    return 0.5f * v * (1.0f + tanhf(0.7978845608028654f * (v + 0.044715f * v * v * v)));
}

// ---------------- weight transpose+convert (coalesced 16B stores) ----------
__global__ __launch_bounds__(256) void wtrans_kernel(const float* __restrict__ W,
                                                     half* __restrict__ Wt,
                                                     int K, int N) {
    __shared__ float tile[64][33];
    const size_t lsz = (size_t)K * N;
    const float* Wl = W + blockIdx.z * lsz;
    half* Wtl = Wt + blockIdx.z * lsz;
    const int n0 = blockIdx.x * 32, k0 = blockIdx.y * 64;
    const int t = threadIdx.x;
    {
        int col = t & 31, r = t >> 5;
#pragma unroll
        for (int i = 0; i < 8; i++)
            tile[r + i * 8][col] = Wl[(size_t)(k0 + r + i * 8) * N + n0 + col];
    }
    __syncthreads();
    {
        int nrow = t >> 3, kc = (t & 7) * 8;
        half2 hv[4];
#pragma unroll
        for (int j = 0; j < 4; j++)
            hv[j] = __floats2half2_rn(tile[kc + 2 * j][nrow], tile[kc + 2 * j + 1][nrow]);
        *(uint4*)&Wtl[(size_t)(n0 + nrow) * K + k0 + kc] = *(uint4*)hv;
    }
}

// ---------------- emb hi/lo split ----------------
__global__ __launch_bounds__(256) void esplit_kernel(const float* __restrict__ src,
                                                     half* __restrict__ hi,
                                                     half* __restrict__ lo) {
    int idx = blockIdx.x * 256 + threadIdx.x;
    float4 v = ((const float4*)src)[idx];
    half h0 = __float2half_rn(v.x), h1 = __float2half_rn(v.y);
    half h2 = __float2half_rn(v.z), h3 = __float2half_rn(v.w);
    half2 hh0; hh0.x = h0; hh0.y = h1;
    half2 hh1; hh1.x = h2; hh1.y = h3;
    *(half2*)(hi + idx * 4) = hh0; *(half2*)(hi + idx * 4 + 2) = hh1;
    *(half2*)(lo + idx * 4) =
        __floats2half2_rn(v.x - __half2float(h0), v.y - __half2float(h1));
    *(half2*)(lo + idx * 4 + 2) =
        __floats2half2_rn(v.z - __half2float(h2), v.w - __half2float(h3));
}

// ---------------- embedding ----------------
__global__ __launch_bounds__(256) void embed_kernel(const int* __restrict__ ids,
                                                    const float* __restrict__ emb,
                                                    float* __restrict__ out) {
    int m = blockIdx.x, t = threadIdx.x;
    int id = ids[m];
    ((float4*)(out + (size_t)m * Hx))[t] = ((const float4*)(emb + (size_t)id * Hx))[t];
}

// ---------------- layernorm: warp-per-row; MODE 1=half, 2=hi/lo halves ------
template<int MODE>
__global__ __launch_bounds__(256) void ln_kernel(const float* __restrict__ x,
                                                 const float* __restrict__ g,
                                                 const float* __restrict__ b,
                                                 half* __restrict__ outh,
                                                 half* __restrict__ outl) {
    const int lane = threadIdx.x & 31;
    const int m = blockIdx.x * 8 + (threadIdx.x >> 5);
    const float4* xr = (const float4*)(x + (size_t)m * Hx);

    float4 v[8];
    float s = 0.f;
#pragma unroll
    for (int i = 0; i < 8; i++) {
        v[i] = xr[lane + i * 32];
        s += v[i].x + v[i].y + v[i].z + v[i].w;
    }
#pragma unroll
    for (int o = 16; o; o >>= 1) s += __shfl_xor_sync(0xffffffffu, s, o);
    float mu = s * (1.0f / Hx);

    float s2 = 0.f;
#pragma unroll
    for (int i = 0; i < 8; i++) {
        float d0 = v[i].x - mu, d1 = v[i].y - mu, d2 = v[i].z - mu, d3 = v[i].w - mu;
        s2 += d0*d0 + d1*d1 + d2*d2 + d3*d3;
    }
#pragma unroll
    for (int o = 16; o; o >>= 1) s2 += __shfl_xor_sync(0xffffffffu, s2, o);
    float inv = rsqrtf(s2 * (1.0f / Hx) + 1e-5f);

#pragma unroll
    for (int i = 0; i < 8; i++) {
        float4 gg = ((const float4*)g)[lane + i * 32];
        float4 bb = ((const float4*)b)[lane + i * 32];
        float o0 = (v[i].x - mu) * inv * gg.x + bb.x;
        float o1 = (v[i].y - mu) * inv * gg.y + bb.y;
        float o2 = (v[i].z - mu) * inv * gg.z + bb.z;
        float o3 = (v[i].w - mu) * inv * gg.w + bb.w;
        int c = (lane + i * 32) * 4;
        if (MODE == 1) {
            *(half2*)(outh + (size_t)m * Hx + c) = __floats2half2_rn(o0, o1);
            *(half2*)(outh + (size_t)m * Hx + c + 2) = __floats2half2_rn(o2, o3);
        } else {
            half h0 = __float2half_rn(o0), h1 = __float2half_rn(o1);
            half h2 = __float2half_rn(o2), h3 = __float2half_rn(o3);
            half2 hh0; hh0.x = h0; hh0.y = h1;
            half2 hh1; hh1.x = h2; hh1.y = h3;
            *(half2*)(outh + (size_t)m * Hx + c) = hh0;
            *(half2*)(outh + (size_t)m * Hx + c + 2) = hh1;
            *(half2*)(outl + (size_t)m * Hx + c) =
                __floats2half2_rn(o0 - __half2float(h0), o1 - __half2float(h1));
            *(half2*)(outl + (size_t)m * Hx + c + 2) =
                __floats2half2_rn(o2 - __half2float(h2), o3 - __half2float(h3));
        }
    }
}

// ======= fp16 GEMM, 4-stage cp.async + ldmatrix =============================
#define HST 40
#define NSTAGE 4
#define STG_HALVES (128 * HST)
#define GEMM_SMEM (NSTAGE * 2 * STG_HALVES * 2)

template<bool GELU, bool RESID, bool OUT_HALF>
__global__ __launch_bounds__(256, 2) void gemm_h16(const half* __restrict__ A,
                                                   const half* __restrict__ Bw,
                                                   const float* __restrict__ bias,
                                                   const float* __restrict__ R,
                                                   float* __restrict__ C,
                                                   half* __restrict__ Ch,
                                                   int M, int N, int K) {
    extern __shared__ half smh[];
    const int t = threadIdx.x;
    const int warp = t >> 5, lane = t & 31;
    const int g = lane >> 2, q = lane & 3;
    const int wm = warp >> 1, wn = warp & 1;
    const int m0 = blockIdx.y * 128, n0 = blockIdx.x * 128;

    const int f_row = t >> 1, f_ch = (t & 1) * 16;
    const uint32_t smbase = (uint32_t)__cvta_generic_to_shared(smh);

    const int a_off = (wm * 32 + (lane & 15)) * HST + (lane >> 4) * 8;
    const int b_off = (wn * 64 + ((lane >> 4) * 8) + (lane & 7)) * HST + ((lane >> 3) & 1) * 8;

    float acc[2][8][4];
#pragma unroll
    for (int mt = 0; mt < 2; mt++)
#pragma unroll
        for (int nt = 0; nt < 8; nt++)
#pragma unroll
            for (int r = 0; r < 4; r++) acc[mt][nt][r] = 0.f;

    const half* Arow = A + (size_t)(m0 + f_row) * K + f_ch;
    const half* Brow = Bw + (size_t)(n0 + f_row) * K + f_ch;

#pragma unroll
    for (int s = 0; s < NSTAGE - 1; s++) {
        half* as = smh + s * 2 * STG_HALVES;
        half* bs = as + STG_HALVES;
        cp_async16(&as[f_row * HST + f_ch],     Arow + s * 32);
        cp_async16(&as[f_row * HST + f_ch + 8], Arow + s * 32 + 8);
        cp_async16(&bs[f_row * HST + f_ch],     Brow + s * 32);
        cp_async16(&bs[f_row * HST + f_ch + 8], Brow + s * 32 + 8);
        cp_commit();
    }

    const int T = K >> 5;
    for (int i = 0; i < T; i++) {
        const int s = i & (NSTAGE - 1);
        cp_wait2();
        __syncthreads();

        if (i + NSTAGE - 1 < T) {
            const int sn = (i + NSTAGE - 1) & (NSTAGE - 1);
            const int kn = (i + NSTAGE - 1) * 32;
            half* as = smh + sn * 2 * STG_HALVES;
            half* bs = as + STG_HALVES;
            cp_async16(&as[f_row * HST + f_ch],     Arow + kn);
            cp_async16(&as[f_row * HST + f_ch + 8], Arow + kn + 8);
            cp_async16(&bs[f_row * HST + f_ch],     Brow + kn);
            cp_async16(&bs[f_row * HST + f_ch + 8], Brow + kn + 8);
        }
        cp_commit();

        const uint32_t as_b = smbase + (uint32_t)(s * 2 * STG_HALVES) * 2;
        const uint32_t bs_b = as_b + (uint32_t)STG_HALVES * 2;
#pragma unroll
        for (int ks = 0; ks < 2; ks++) {
            const int k = ks * 16;
            uint32_t af[2][4], bf[8][2];
#pragma unroll
            for (int mt = 0; mt < 2; mt++)
                ldsm_x4(af[mt][0], af[mt][1], af[mt][2], af[mt][3],
                        as_b + (uint32_t)(a_off + mt * 16 * HST + k) * 2);
#pragma unroll
            for (int p = 0; p < 4; p++)
                ldsm_x4(bf[2*p][0], bf[2*p][1], bf[2*p+1][0], bf[2*p+1][1],
                        bs_b + (uint32_t)(b_off + p * 16 * HST + k) * 2);
#pragma unroll
            for (int mt = 0; mt < 2; mt++)
#pragma unroll
                for (int nt = 0; nt < 8; nt++)
                    mma_f16(acc[mt][nt], af[mt], bf[nt]);
        }
    }

#pragma unroll
    for (int mt = 0; mt < 2; mt++) {
#pragma unroll
        for (int nt = 0; nt < 8; nt++) {
            int r0 = m0 + wm * 32 + mt * 16 + g;
            int c0 = n0 + wn * 64 + nt * 8 + q * 2;
            float b0 = bias ? bias[c0] : 0.f;
            float b1 = bias ? bias[c0 + 1] : 0.f;
#pragma unroll
            for (int hf = 0; hf < 2; hf++) {
                int row = r0 + hf * 8;
                float v0 = acc[mt][nt][hf * 2 + 0] + b0;
                float v1 = acc[mt][nt][hf * 2 + 1] + b1;
                if (GELU) { v0 = gelu_f(v0); v1 = gelu_f(v1); }
                if (RESID) {
                    const float2 rr = *(const float2*)(R + (size_t)row * N + c0);
                    v0 += rr.x; v1 += rr.y;
                }
                if (OUT_HALF) {
                    *(half2*)(Ch + (size_t)row * N + c0) = __floats2half2_rn(v0, v1);
                } else {
                    float2 o2; o2.x = v0; o2.y = v1;
                    *(float2*)(C + (size_t)row * N + c0) = o2;
                }
            }
        }
    }
}

// ---- fused flash attention: fp16 HMMA, 64-q tiles + masked-tile skip -------
#define AHS 72
#define ATTN_SMEM_BYTES (4 * 64 * AHS * 2)   // 36864

__global__ __launch_bounds__(128) void attn_kernel(const half* __restrict__ qkv,
                                                   const int* __restrict__ sp,
                                                   half* __restrict__ attn) {
    extern __shared__ half smah[];
    half* Qs = smah;
    half* Ks = Qs + 64 * AHS;
    half* Vs = Ks + 64 * AHS;
    half* Ps = Vs + 64 * AHS;
    const uint32_t qs_b = (uint32_t)__cvta_generic_to_shared(Qs);
    const uint32_t ks_b = (uint32_t)__cvta_generic_to_shared(Ks);
    const uint32_t vs_b = (uint32_t)__cvta_generic_to_shared(Vs);
    const uint32_t ps_b = (uint32_t)__cvta_generic_to_shared(Ps);

    const int it = blockIdx.x, bn = blockIdx.y;
    const int b = bn >> 4, n = bn & 15;
    const int t = threadIdx.x, w = t >> 5, lane = t & 31;
    const int g = lane >> 2, q = lane & 3;
    const int i0 = it * 64;
    const int spv = sp[b];
    const float slope2 = exp2f(-0.5f * (float)(n + 1)) * LOG2E;
    const float qs2 = 0.125f * LOG2E;

#pragma unroll
    for (int l = 0; l < 4; l++) {
        int e = t + l * 128;
        int row = e >> 3, c8 = (e & 7) * 8;
        cp_async16(&Qs[row * AHS + c8],
                   qkv + (size_t)(b * Sx + i0 + row) * 3072 + n * 64 + c8);
    }
    cp_commit();
    cp_wait0();
    __syncthreads();

    const int r0 = w * 16 + g;
    const int a_off = (w * 16 + (lane & 15)) * AHS + (lane >> 4) * 8;
    uint32_t qf[4][4];
#pragma unroll
    for (int kk = 0; kk < 4; kk++)
        ldsm_x4(qf[kk][0], qf[kk][1], qf[kk][2], qf[kk][3],
                qs_b + (uint32_t)(a_off + kk * 16) * 2);

    const int bk_off = (((lane >> 4) * 8) + (lane & 7)) * AHS + ((lane >> 3) & 1) * 8;
    const int vt_off = (((lane >> 3) & 1) * 8 + (lane & 7)) * AHS + (lane >> 4) * 8;

    float o[8][4];
#pragma unroll
    for (int nt = 0; nt < 8; nt++)
#pragma unroll
        for (int c = 0; c < 4; c++) o[nt][c] = 0.f;
    float m0 = -1e30f, m1 = -1e30f, l0 = 0.f, l1 = 0.f;

    const int rowA = i0 + r0, rowB = rowA + 8;

    for (int jt = 0; jt <= it; jt++) {
        const int j0 = jt * 64;
        // fully-masked tile skip (CTA-uniform; contributes exactly zero)
        if (i0 >= spv && j0 + 64 <= spv) continue;

        __syncthreads();   // previous PV done -> Ks/Vs reusable
#pragma unroll
        for (int l = 0; l < 4; l++) {
            int e = t + l * 128;
            int row = e >> 3, c8 = (e & 7) * 8;
            const half* base = qkv + (size_t)(b * Sx + j0 + row) * 3072 + n * 64 + c8;
            cp_async16(&Ks[row * AHS + c8], base + 1024);
            cp_async16(&Vs[row * AHS + c8], base + 2048);
        }
        cp_commit();
        cp_wait0();
        __syncthreads();

        // ---- QK^T
        float s[8][4];
#pragma unroll
        for (int nt = 0; nt < 8; nt++)
#pragma unroll
            for (int c = 0; c < 4; c++) s[nt][c] = 0.f;
#pragma unroll
        for (int kk = 0; kk < 4; kk++) {
            uint32_t bf[8][2];
#pragma unroll
            for (int p = 0; p < 4; p++)
                ldsm_x4(bf[2*p][0], bf[2*p][1], bf[2*p+1][0], bf[2*p+1][1],
                        ks_b + (uint32_t)(bk_off + p * 16 * AHS + kk * 16) * 2);
#pragma unroll
            for (int nt = 0; nt < 8; nt++)
                mma_f16(s[nt], qf[kk], bf[nt]);
        }

        // ---- scale + bias + mask (log2 domain)
#pragma unroll
        for (int nt = 0; nt < 8; nt++) {
#pragma unroll
            for (int c = 0; c < 4; c++) {
                int i = (c < 2) ? rowA : rowB;
                int j = j0 + nt * 8 + 2 * q + (c & 1);
                bool allowed = (j <= i) && !((i >= spv) && (j < spv));
                s[nt][c] = allowed ? fmaf(s[nt][c], qs2, -slope2 * (float)(i - j)) : -1e30f;
            }
        }

        // ---- online softmax
        float mx0 = -1e30f, mx1 = -1e30f;
#pragma unroll
        for (int nt = 0; nt < 8; nt++) {
            mx0 = fmaxf(mx0, fmaxf(s[nt][0], s[nt][1]));
            mx1 = fmaxf(mx1, fmaxf(s[nt][2], s[nt][3]));
        }
        mx0 = fmaxf(mx0, __shfl_xor_sync(0xffffffffu, mx0, 1));
        mx0 = fmaxf(mx0, __shfl_xor_sync(0xffffffffu, mx0, 2));
        mx1 = fmaxf(mx1, __shfl_xor_sync(0xffffffffu, mx1, 1));
        mx1 = fmaxf(mx1, __shfl_xor_sync(0xffffffffu, mx1, 2));
        float mn0 = fmaxf(m0, mx0), mn1 = fmaxf(m1, mx1);
        float al0 = ex2(m0 - mn0), al1 = ex2(m1 - mn1);

        float sum0 = 0.f, sum1 = 0.f;
#pragma unroll
        for (int nt = 0; nt < 8; nt++) {
            float p0 = ex2(s[nt][0] - mn0);
            float p1 = ex2(s[nt][1] - mn0);
            float p2 = ex2(s[nt][2] - mn1);
            float p3 = ex2(s[nt][3] - mn1);
            sum0 += p0 + p1; sum1 += p2 + p3;
            *(half2*)&Ps[(r0    ) * AHS + nt * 8 + 2 * q] = __floats2half2_rn(p0, p1);
            *(half2*)&Ps[(r0 + 8) * AHS + nt * 8 + 2 * q] = __floats2half2_rn(p2, p3);
        }
        sum0 += __shfl_xor_sync(0xffffffffu, sum0, 1);
        sum0 += __shfl_xor_sync(0xffffffffu, sum0, 2);
        sum1 += __shfl_xor_sync(0xffffffffu, sum1, 1);
        sum1 += __shfl_xor_sync(0xffffffffu, sum1, 2);
        l0 = l0 * al0 + sum0;
        l1 = l1 * al1 + sum1;
        m0 = mn0; m1 = mn1;
#pragma unroll
        for (int nt = 0; nt < 8; nt++) {
            o[nt][0] *= al0; o[nt][1] *= al0;
            o[nt][2] *= al1; o[nt][3] *= al1;
        }
        __syncwarp();

        // ---- P @ V
#pragma unroll
        for (int kk = 0; kk < 4; kk++) {
            uint32_t pf[4];
            ldsm_x4(pf[0], pf[1], pf[2], pf[3],
                    ps_b + (uint32_t)(a_off + kk * 16) * 2);
            uint32_t bf[8][2];
#pragma unroll
            for (int p = 0; p < 4; p++)
                ldsm_x4_t(bf[2*p][0], bf[2*p][1], bf[2*p+1][0], bf[2*p+1][1],
                          vs_b + (uint32_t)(vt_off + kk * 16 * AHS + p * 16) * 2);
#pragma unroll
            for (int nt = 0; nt < 8; nt++)
                mma_f16(o[nt], pf, bf[nt]);
        }
    }

    const float inv0 = 1.0f / l0, inv1 = 1.0f / l1;
#pragma unroll
    for (int nt = 0; nt < 8; nt++) {
        *(half2*)(attn + (size_t)(b * Sx + rowA) * Hx + n * 64 + nt * 8 + 2 * q) =
            __floats2half2_rn(o[nt][0] * inv0, o[nt][1] * inv0);
        *(half2*)(attn + (size_t)(b * Sx + rowB) * Hx + n * 64 + nt * 8 + 2 * q) =
            __floats2half2_rn(o[nt][2] * inv1, o[nt][3] * inv1);
    }
}

// ---------------- logits: fp16 hi/lo 3-term GEMM, 2-stage ------------------
#define L3_STG (128 * HST)
#define L3_STAGE (4 * L3_STG)
#define L3_SMEM (2 * L3_STAGE * 2)

__global__ __launch_bounds__(256) void gemm_logits3(const half* __restrict__ Ahi,
                                                    const half* __restrict__ Alo,
                                                    const half* __restrict__ Bhi,
                                                    const half* __restrict__ Blo,
                                                    float* __restrict__ C,
                                                    int M, int N, int K) {
    extern __shared__ half smh[];
    const int t = threadIdx.x;
    const int warp = t >> 5, lane = t & 31;
    const int g = lane >> 2, q = lane & 3;
    const int wm = warp >> 1, wn = warp & 1;
    const int m0 = blockIdx.y * 128, n0 = blockIdx.x * 128;

    const int f_row = t >> 1, f_ch = (t & 1) * 16;
    const uint32_t smbase = (uint32_t)__cvta_generic_to_shared(smh);

    const int a_off = (wm * 32 + (lane & 15)) * HST + (lane >> 4) * 8;
    const int b_off = (wn * 64 + ((lane >> 4) * 8) + (lane & 7)) * HST + ((lane >> 3) & 1) * 8;

    float acc[2][8][4];
#pragma unroll
    for (int mt = 0; mt < 2; mt++)
#pragma unroll
        for (int nt = 0; nt < 8; nt++)
#pragma unroll
            for (int r = 0; r < 4; r++) acc[mt][nt][r] = 0.f;

    const half* ArH = Ahi + (size_t)(m0 + f_row) * K + f_ch;
    const half* ArL = Alo + (size_t)(m0 + f_row) * K + f_ch;
    const half* BrH = Bhi + (size_t)(n0 + f_row) * K + f_ch;
    const half* BrL = Blo + (size_t)(n0 + f_row) * K + f_ch;
    const int so = f_row * HST + f_ch;

    {
        half* st = smh;
        cp_async16(&st[so], ArH);                     cp_async16(&st[so + 8], ArH + 8);
        cp_async16(&st[L3_STG + so], ArL);            cp_async16(&st[L3_STG + so + 8], ArL + 8);
        cp_async16(&st[2 * L3_STG + so], BrH);        cp_async16(&st[2 * L3_STG + so + 8], BrH + 8);
        cp_async16(&st[3 * L3_STG + so], BrL);        cp_async16(&st[3 * L3_STG + so + 8], BrL + 8);
        cp_commit();
    }

    const int T = K >> 5;
    for (int i = 0; i < T; i++) {
        cp_wait0();
        __syncthreads();

        if (i + 1 < T) {
            const int kn = (i + 1) * 32;
            half* st = smh + ((i + 1) & 1) * L3_STAGE;
            cp_async16(&st[so], ArH + kn);                cp_async16(&st[so + 8], ArH + kn + 8);
            cp_async16(&st[L3_STG + so], ArL + kn);       cp_async16(&st[L3_STG + so + 8], ArL + kn + 8);
            cp_async16(&st[2 * L3_STG + so], BrH + kn);   cp_async16(&st[2 * L3_STG + so + 8], BrH + kn + 8);
            cp_async16(&st[3 * L3_STG + so], BrL + kn);   cp_async16(&st[3 * L3_STG + so + 8], BrL + kn + 8);
        }
        cp_commit();

        const uint32_t st_b  = smbase + (uint32_t)((i & 1) * L3_STAGE) * 2;
        const uint32_t ah_b = st_b;
        const uint32_t al_b = st_b + (uint32_t)L3_STG * 2;
        const uint32_t bh_b = st_b + (uint32_t)(2 * L3_STG) * 2;
        const uint32_t bl_b = st_b + (uint32_t)(3 * L3_STG) * 2;
#pragma unroll
        for (int ks = 0; ks < 2; ks++) {
            const int k = ks * 16;
            uint32_t ah[2][4], al[2][4], bh[8][2], bl[8][2];
#pragma unroll
            for (int mt = 0; mt < 2; mt++) {
                ldsm_x4(ah[mt][0], ah[mt][1], ah[mt][2], ah[mt][3],
                        ah_b + (uint32_t)(a_off + mt * 16 * HST + k) * 2);
                ldsm_x4(al[mt][0], al[mt][1], al[mt][2], al[mt][3],
                        al_b + (uint32_t)(a_off + mt * 16 * HST + k) * 2);
            }
#pragma unroll
            for (int p = 0; p < 4; p++) {
                ldsm_x4(bh[2*p][0], bh[2*p][1], bh[2*p+1][0], bh[2*p+1][1],
                        bh_b + (uint32_t)(b_off + p * 16 * HST + k) * 2);
                ldsm_x4(bl[2*p][0], bl[2*p][1], bl[2*p+1][0], bl[2*p+1][1],
                        bl_b + (uint32_t)(b_off + p * 16 * HST + k) * 2);
            }
#pragma unroll
            for (int mt = 0; mt < 2; mt++)
#pragma unroll
                for (int nt = 0; nt < 8; nt++) {
                    mma_f16(acc[mt][nt], ah[mt], bl[nt]);
                    mma_f16(acc[mt][nt], al[mt], bh[nt]);
                    mma_f16(acc[mt][nt], ah[mt], bh[nt]);
                }
        }
    }

#pragma unroll
    for (int mt = 0; mt < 2; mt++) {
#pragma unroll
        for (int nt = 0; nt < 8; nt++) {
            int r0 = m0 + wm * 32 + mt * 16 + g;
            int c0 = n0 + wn * 64 + nt * 8 + q * 2;
#pragma unroll
            for (int hf = 0; hf < 2; hf++) {
                int row = r0 + hf * 8;
                float2 o2;
                o2.x = acc[mt][nt][hf * 2 + 0];
                o2.y = acc[mt][nt][hf * 2 + 1];
                *(float2*)(C + (size_t)row * N + c0) = o2;
            }
        }
    }
}

// ---------------- launcher ----------------
extern "C" void kernel_launch(void* const* d_in, const int* in_sizes, int n_in,
                              void* d_out, int out_size) {
    const int*   ids    = (const int*)d_in[0];
    const int*   sp     = (const int*)d_in[1];
    const float* emb    = (const float*)d_in[2];
    const float* ln1_g  = (const float*)d_in[3];
    const float* ln1_b  = (const float*)d_in[4];
    const float* Wqkv   = (const float*)d_in[5];
    const float* bqkv   = (const float*)d_in[6];
    const float* Wo     = (const float*)d_in[7];
    const float* bo     = (const float*)d_in[8];
    const float* ln2_g  = (const float*)d_in[9];
    const float* ln2_b  = (const float*)d_in[10];
    const float* Wfc    = (const float*)d_in[11];
    const float* bfc    = (const float*)d_in[12];
    const float* Wproj  = (const float*)d_in[13];
    const float* bproj  = (const float*)d_in[14];
    const float* lnf_g  = (const float*)d_in[15];
    const float* lnf_b  = (const float*)d_in[16];
    float* out = (float*)d_out;

    float* x;
    half *qkv_h, *hh, *attn_h, *mid_h, *hhi, *hlo, *ehi, *elo;
    half *wqkv_t, *wo_t, *wfc_t, *wproj_t;
    cudaGetSymbolAddress((void**)&x,       g_x);
    cudaGetSymbolAddress((void**)&qkv_h,   g_qkv_h);
    cudaGetSymbolAddress((void**)&hh,      g_hh);
    cudaGetSymbolAddress((void**)&attn_h,  g_attn_h);
    cudaGetSymbolAddress((void**)&mid_h,   g_mid_h);
    cudaGetSymbolAddress((void**)&hhi,     g_hhi);
    cudaGetSymbolAddress((void**)&hlo,     g_hlo);
    cudaGetSymbolAddress((void**)&ehi,     g_ehi);
    cudaGetSymbolAddress((void**)&elo,     g_elo);
    cudaGetSymbolAddress((void**)&wqkv_t,  g_Wqkv_t);
    cudaGetSymbolAddress((void**)&wo_t,    g_Wo_t);
    cudaGetSymbolAddress((void**)&wfc_t,   g_Wfc_t);
    cudaGetSymbolAddress((void**)&wproj_t, g_Wproj_t);

    cudaFuncSetAttribute(attn_kernel, cudaFuncAttributeMaxDynamicSharedMemorySize, ATTN_SMEM_BYTES);
    cudaFuncSetAttribute(gemm_h16<false, false, true>,  cudaFuncAttributeMaxDynamicSharedMemorySize, GEMM_SMEM);
    cudaFuncSetAttribute(gemm_h16<false, true, false>,  cudaFuncAttributeMaxDynamicSharedMemorySize, GEMM_SMEM);
    cudaFuncSetAttribute(gemm_h16<true, false, true>,   cudaFuncAttributeMaxDynamicSharedMemorySize, GEMM_SMEM);
    cudaFuncSetAttribute(gemm_logits3, cudaFuncAttributeMaxDynamicSharedMemorySize, L3_SMEM);

    wtrans_kernel<<<dim3(3 * Hx / 32, Hx / 64, NLx), 256>>>(Wqkv, wqkv_t, Hx, 3 * Hx);
    wtrans_kernel<<<dim3(Hx / 32, Hx / 64, NLx), 256>>>(Wo, wo_t, Hx, Hx);
    wtrans_kernel<<<dim3(Fx / 32, Hx / 64, NLx), 256>>>(Wfc, wfc_t, Hx, Fx);
    wtrans_kernel<<<dim3(Hx / 32, Fx / 64, NLx), 256>>>(Wproj, wproj_t, Fx, Hx);
    esplit_kernel<<<(Vx * Hx / 4) / 256, 256>>>(emb, ehi, elo);

    embed_kernel<<<Mx, 256>>>(ids, emb, x);

    for (int l = 0; l < NLx; l++) {
        ln_kernel<1><<<Mx / 8, 256>>>(x, ln1_g + l * Hx, ln1_b + l * Hx, hh, nullptr);
        gemm_h16<false, false, true><<<dim3(3 * Hx / 128, Mx / 128), 256, GEMM_SMEM>>>(
            hh, wqkv_t + (size_t)l * 3 * Hx * Hx, bqkv + (size_t)l * 3 * Hx, nullptr,
            nullptr, qkv_h, Mx, 3 * Hx, Hx);
        attn_kernel<<<dim3(Sx / 64, Bx * NHx), 128, ATTN_SMEM_BYTES>>>(qkv_h, sp, attn_h);
        gemm_h16<false, true, false><<<dim3(Hx / 128, Mx / 128), 256, GEMM_SMEM>>>(
            attn_h, wo_t + (size_t)l * Hx * Hx, bo + (size_t)l * Hx, x,
            x, nullptr, Mx, Hx, Hx);
        ln_kernel<1><<<Mx / 8, 256>>>(x, ln2_g + l * Hx, ln2_b + l * Hx, hh, nullptr);
        gemm_h16<true, false, true><<<dim3(Fx / 128, Mx / 128), 256, GEMM_SMEM>>>(
            hh, wfc_t + (size_t)l * Fx * Hx, bfc + (size_t)l * Fx, nullptr,
            nullptr, mid_h, Mx, Fx, Hx);
        gemm_h16<false, true, false><<<dim3(Hx / 128, Mx / 128), 256, GEMM_SMEM>>>(
            mid_h, wproj_t + (size_t)l * Hx * Fx, bproj + (size_t)l * Hx, x,
            x, nullptr, Mx, Hx, Fx);
    }

    ln_kernel<2><<<Mx / 8, 256>>>(x, lnf_g, lnf_b, hhi, hlo);
    gemm_logits3<<<dim3(Vx / 128, Mx / 128), 256, L3_SMEM>>>(
        hhi, hlo, ehi, elo, out, Mx, Vx, Hx);
}